// round 15
// baseline (speedup 1.0000x reference)
#include <cuda_runtime.h>
#include <cuda_bf16.h>
#include <cuda_fp8.h>
#include <cstdint>
#include <math.h>

#define NU 200000
#define NP 100000
#define NN 300000
#define NE 1000000
#define CAP 64             // adjacency slots per node (Poisson(~6.7): overflow impossible)
#define STRIDE 72          // bf16 units, padded row stride for 64-col smem tiles
#define XSTR 136           // bf16 units, padded row stride for 128-col feat tile
#define GU 1563            // ceil(NU/128)
#define GP 782             // ceil(NP/128)
#define GU2 782            // ceil(NU/256)  (mm: 256 rows/block)
#define GP2 391            // ceil(NP/256)

// Scratch (module-static device memory; sanctioned by harness rules)
__device__ __nv_bfloat162 g_xb[(size_t)NN * 32];     // GEMM inputs (bf16)
__device__ unsigned short g_h8[(size_t)NN * 32];     // messages / projections (fp8x2 e4m3)
__device__ int            g_cnt[NN];
__device__ int            g_adj[(size_t)NN * CAP];

// ---------------------------------------------------------------------------
// helpers
// ---------------------------------------------------------------------------
__device__ __forceinline__ unsigned pack_bf2(float x, float y) {
    __nv_bfloat162 h = __floats2bfloat162_rn(x, y);
    return *(unsigned*)&h;
}
__device__ __forceinline__ unsigned short f2_to_fp8x2(float x, float y) {
    float2 f = make_float2(x, y);
    return (unsigned short)__nv_cvt_float2_to_fp8x2(f, __NV_SATFINITE, __NV_E4M3);
}
__device__ __forceinline__ float2 fp8x2_to_f2(unsigned short v) {
    __half2_raw hr = __nv_cvt_fp8x2_to_halfraw2((__nv_fp8x2_storage_t)v, __NV_E4M3);
    return __half22float2(*(__half2*)&hr);
}

__device__ __forceinline__ void ldmA(uint32_t addr, uint32_t& a0, uint32_t& a1,
                                     uint32_t& a2, uint32_t& a3) {
    asm volatile("ldmatrix.sync.aligned.m8n8.x4.shared.b16 {%0,%1,%2,%3},[%4];"
                 : "=r"(a0), "=r"(a1), "=r"(a2), "=r"(a3) : "r"(addr));
}
__device__ __forceinline__ void ldmBT(uint32_t addr, uint32_t& b0, uint32_t& b1,
                                      uint32_t& b2, uint32_t& b3) {
    asm volatile("ldmatrix.sync.aligned.m8n8.x4.trans.shared.b16 {%0,%1,%2,%3},[%4];"
                 : "=r"(b0), "=r"(b1), "=r"(b2), "=r"(b3) : "r"(addr));
}
__device__ __forceinline__ void mma16816(float* c, uint32_t a0, uint32_t a1,
                                         uint32_t a2, uint32_t a3,
                                         uint32_t b0, uint32_t b1) {
    asm volatile("mma.sync.aligned.m16n8k16.row.col.f32.bf16.bf16.f32 "
                 "{%0,%1,%2,%3},{%4,%5,%6,%7},{%8,%9},{%0,%1,%2,%3};"
                 : "+f"(c[0]), "+f"(c[1]), "+f"(c[2]), "+f"(c[3])
                 : "r"(a0), "r"(a1), "r"(a2), "r"(a3), "r"(b0), "r"(b1));
}

// K-chunked core: C[warp 16 rows x 64 cols] += A[16 x 16*KS] @ B[16*KS x 64]
template<int KS, int ASTR>
__device__ __forceinline__ void mma_core_t(uint32_t xtw, uint32_t wtb, int l,
                                           float cf[8][4]) {
    uint32_t arow = (uint32_t)(((l & 7) + ((l >> 3) & 1) * 8));
    uint32_t aAddr = xtw + (arow * ASTR + (uint32_t)(l >> 4) * 8) * 2;
    uint32_t bAddr = wtb + (arow * STRIDE + (uint32_t)(l >> 4) * 8) * 2;
    #pragma unroll
    for (int ks = 0; ks < KS; ks++) {
        uint32_t a0, a1, a2, a3;
        ldmA(aAddr + ks * 32, a0, a1, a2, a3);
        #pragma unroll
        for (int np = 0; np < 4; np++) {
            uint32_t b0, b1, b2, b3;
            ldmBT(bAddr + (uint32_t)(ks * 16 * STRIDE + np * 16) * 2, b0, b1, b2, b3);
            mma16816(cf[2 * np],     a0, a1, a2, a3, b0, b1);
            mma16816(cf[2 * np + 1], a0, a1, a2, a3, b2, b3);
        }
    }
}

// ---------------------------------------------------------------------------
// Adjacency build
// ---------------------------------------------------------------------------
__global__ void k_zero() {
    int n = blockIdx.x * blockDim.x + threadIdx.x;
    if (n < NN) g_cnt[n] = 0;
}
__global__ void k_build(const int* __restrict__ ei) {
    int e = blockIdx.x * blockDim.x + threadIdx.x;
    if (e < NE) {
        int u = ei[e];
        int p = ei[NE + e];
        int s1 = atomicAdd(&g_cnt[u], 1);
        if (s1 < CAP) g_adj[(size_t)u * CAP + s1] = p;   // message p -> u
        int s2 = atomicAdd(&g_cnt[p], 1);
        if (s2 < CAP) g_adj[(size_t)p * CAP + s2] = u;   // message u -> p
    }
}

// ---------------------------------------------------------------------------
// Feature projection: g_xb[n] = bf16(feat[n](128) @ W + b + emb[n])
// Single K-pass; 4 CTAs/SM target.
// ---------------------------------------------------------------------------
__global__ __launch_bounds__(256, 4) void k_feat_t(
    const float* __restrict__ uf, const float* __restrict__ pf,
    const float* __restrict__ ue, const float* __restrict__ pe,
    const float* __restrict__ Wuf, const float* __restrict__ buf_,
    const float* __restrict__ Wpf, const float* __restrict__ bpf,
    int bidOff)
{
    __shared__ __align__(16) __nv_bfloat16 xt[128 * XSTR];   // 34.8 KB
    __shared__ __align__(16) __nv_bfloat16 wt[128 * STRIDE]; // 18.4 KB
    __shared__ float bs[64];

    int bid = blockIdx.x + bidOff;
    bool isUser = bid < GU;
    int lrow0 = isUser ? bid * 128 : (bid - GU) * 128;
    int nloc  = isUser ? NU : NP;
    const float* feat = isUser ? uf : pf;
    const float* emb  = isUser ? ue : pe;
    const float* W    = isUser ? Wuf : Wpf;
    const float* b    = isUser ? buf_ : bpf;
    int grow0 = isUser ? lrow0 : NU + lrow0;

    int tid = threadIdx.x;
    if (tid < 32) ((float2*)bs)[tid] = ((const float2*)b)[tid];

    const float4* W4 = (const float4*)W;
    const float4* f4 = (const float4*)feat;   // row stride 32 float4

    // W full (128x64 fp32 = 2048 f4), 8 per thread
    #pragma unroll
    for (int i = 0; i < 8; i++) {
        int idx = tid + i * 256, r = idx >> 4, c4 = idx & 15;
        float4 v = W4[idx];
        *(uint2*)(&wt[r * STRIDE + c4 * 4]) =
            make_uint2(pack_bf2(v.x, v.y), pack_bf2(v.z, v.w));
    }
    // x full (128 rows x 32 f4), 16 per thread
    #pragma unroll
    for (int i = 0; i < 16; i++) {
        int idx = tid + i * 256, r = idx >> 5, c4 = idx & 31;
        int lr = lrow0 + r;
        float4 v = make_float4(0.f, 0.f, 0.f, 0.f);
        if (lr < nloc) v = f4[(size_t)lr * 32 + c4];
        *(uint2*)(&xt[r * XSTR + c4 * 4]) =
            make_uint2(pack_bf2(v.x, v.y), pack_bf2(v.z, v.w));
    }
    __syncthreads();

    int l = tid & 31, w = tid >> 5;
    float cf[8][4];
    #pragma unroll
    for (int j = 0; j < 8; j++)
        #pragma unroll
        for (int q = 0; q < 4; q++) cf[j][q] = 0.f;

    mma_core_t<8, XSTR>(
        (uint32_t)__cvta_generic_to_shared(xt) + (uint32_t)(w * 16 * XSTR) * 2,
        (uint32_t)__cvta_generic_to_shared(wt), l, cf);

    int rl = w * 16 + (l >> 2);
    #pragma unroll
    for (int half = 0; half < 2; half++) {
        int lr = lrow0 + rl + half * 8;
        if (lr < nloc) {
            size_t gr = (size_t)(grow0 + rl + half * 8);
            #pragma unroll
            for (int j = 0; j < 8; j++) {
                int c2 = j * 4 + (l & 3);
                float2 ev = ((const float2*)emb)[(size_t)lr * 32 + c2];
                g_xb[gr * 32 + c2] = __floats2bfloat162_rn(
                    cf[j][half * 2 + 0] + bs[c2 * 2]     + ev.x,
                    cf[j][half * 2 + 1] + bs[c2 * 2 + 1] + ev.y);
            }
        }
    }
}

// ---------------------------------------------------------------------------
// k_mm: g_h8[n] = fp8( (g_xb[n] @ W) * (epiDis ? dis[n] : 1) )
// 256 rows/block (two 128-row tiles share one weight load).
// ---------------------------------------------------------------------------
__global__ __launch_bounds__(256) void k_mm(
    const float* __restrict__ Wu, const float* __restrict__ Wp, int epiDis,
    int bidOff)
{
    __shared__ __align__(16) __nv_bfloat16 xt[128 * STRIDE];
    __shared__ __align__(16) __nv_bfloat16 wt[64 * STRIDE];

    int bid = blockIdx.x + bidOff;
    bool isUser = bid < GU2;
    int lrow00 = isUser ? bid * 256 : (bid - GU2) * 256;
    int nloc  = isUser ? NU : NP;
    int gbase = isUser ? 0 : NU;
    const float* W = isUser ? Wu : Wp;

    int tid = threadIdx.x;
    #pragma unroll
    for (int i = 0; i < 4; i++) {
        int idx = tid + i * 256, r = idx >> 4, c4 = idx & 15;
        float4 v = ((const float4*)W)[idx];
        *(uint2*)(&wt[r * STRIDE + c4 * 4]) =
            make_uint2(pack_bf2(v.x, v.y), pack_bf2(v.z, v.w));
    }

    int l = tid & 31, w = tid >> 5;
    const uint4* x4 = (const uint4*)g_xb;

    #pragma unroll
    for (int t = 0; t < 2; t++) {
        int lrow0 = lrow00 + t * 128;
        __syncthreads();
        #pragma unroll
        for (int i = 0; i < 4; i++) {
            int idx = tid + i * 256, r = idx >> 3, c = idx & 7;
            int lr = lrow0 + r;
            uint4 v = make_uint4(0u, 0u, 0u, 0u);
            if (lr < nloc) v = x4[(size_t)(gbase + lr) * 8 + c];
            *(uint4*)(&xt[r * STRIDE + c * 8]) = v;
        }
        __syncthreads();

        float cf[8][4];
        #pragma unroll
        for (int j = 0; j < 8; j++)
            #pragma unroll
            for (int q = 0; q < 4; q++) cf[j][q] = 0.f;

        mma_core_t<4, STRIDE>(
            (uint32_t)__cvta_generic_to_shared(xt) + (uint32_t)(w * 16 * STRIDE) * 2,
            (uint32_t)__cvta_generic_to_shared(wt), l, cf);

        int rl = w * 16 + (l >> 2);
        #pragma unroll
        for (int half = 0; half < 2; half++) {
            int lr = lrow0 + rl + half * 8;
            if (lr < nloc) {
                int gr = gbase + lr;
                float d = epiDis ? rsqrtf((float)(g_cnt[gr] + 1)) : 1.f;
                #pragma unroll
                for (int j = 0; j < 8; j++) {
                    int c2 = j * 4 + (l & 3);
                    g_h8[(size_t)gr * 32 + c2] = f2_to_fp8x2(
                        cf[j][half * 2 + 0] * d, cf[j][half * 2 + 1] * d);
                }
            }
        }
    }
}

// ---------------------------------------------------------------------------
// k_agg: g_xb[n] = act( b + dis[n] * (g_h8[n] + sum_{src in adj[n]} g_h8[src]) )
// QUARTER-warp per node (fp8 rows are 64B = 8 lanes x 8B); 4 nodes per warp.
// ---------------------------------------------------------------------------
__global__ __launch_bounds__(256) void k_agg(const float* __restrict__ b,
                                             int doRelu, int nodeBase, int nNodes)
{
    int ln = blockIdx.x * 32 + (threadIdx.x >> 3);
    if (ln >= nNodes) return;
    int n = nodeBase + ln;
    int lane = threadIdx.x & 7;           // 8 fp8 cols => cols [8l,8l+8)
    int c = g_cnt[n];
    if (c > CAP) c = CAP;
    float d = rsqrtf((float)(c + 1));
    const uint2* h64 = (const uint2*)g_h8;   // 8B = 8 fp8 values
    uint2 own = h64[(size_t)n * 8 + lane];
    float2 s0v = fp8x2_to_f2((unsigned short)(own.x & 0xffffu));
    float2 s1v = fp8x2_to_f2((unsigned short)(own.x >> 16));
    float2 s2v = fp8x2_to_f2((unsigned short)(own.y & 0xffffu));
    float2 s3v = fp8x2_to_f2((unsigned short)(own.y >> 16));
    float sx0 = s0v.x, sy0 = s0v.y, sx1 = s1v.x, sy1 = s1v.y;
    float sx2 = s2v.x, sy2 = s2v.y, sx3 = s3v.x, sy3 = s3v.y;
    size_t base = (size_t)n * CAP;
    for (int i0 = 0; i0 < c; i0 += 8) {
        int m = min(8, c - i0);
        int srcl = (lane < m) ? g_adj[base + i0 + lane] : 0;
        int i = 0;
        for (; i + 3 < m; i += 4) {
            int a0 = __shfl_sync(0xffffffffu, srcl, i,     8);
            int a1 = __shfl_sync(0xffffffffu, srcl, i + 1, 8);
            int a2 = __shfl_sync(0xffffffffu, srcl, i + 2, 8);
            int a3 = __shfl_sync(0xffffffffu, srcl, i + 3, 8);
            uint2 r0 = h64[(size_t)a0 * 8 + lane];
            uint2 r1 = h64[(size_t)a1 * 8 + lane];
            uint2 r2 = h64[(size_t)a2 * 8 + lane];
            uint2 r3 = h64[(size_t)a3 * 8 + lane];
            #pragma unroll
            for (int q = 0; q < 4; q++) {
                uint2 rr = (q == 0) ? r0 : (q == 1) ? r1 : (q == 2) ? r2 : r3;
                float2 f0 = fp8x2_to_f2((unsigned short)(rr.x & 0xffffu));
                float2 f1 = fp8x2_to_f2((unsigned short)(rr.x >> 16));
                float2 f2 = fp8x2_to_f2((unsigned short)(rr.y & 0xffffu));
                float2 f3 = fp8x2_to_f2((unsigned short)(rr.y >> 16));
                sx0 += f0.x; sy0 += f0.y;
                sx1 += f1.x; sy1 += f1.y;
                sx2 += f2.x; sy2 += f2.y;
                sx3 += f3.x; sy3 += f3.y;
            }
        }
        for (; i < m; i++) {
            int a0 = __shfl_sync(0xffffffffu, srcl, i, 8);
            uint2 r0 = h64[(size_t)a0 * 8 + lane];
            float2 f0 = fp8x2_to_f2((unsigned short)(r0.x & 0xffffu));
            float2 f1 = fp8x2_to_f2((unsigned short)(r0.x >> 16));
            float2 f2 = fp8x2_to_f2((unsigned short)(r0.y & 0xffffu));
            float2 f3 = fp8x2_to_f2((unsigned short)(r0.y >> 16));
            sx0 += f0.x; sy0 += f0.y;
            sx1 += f1.x; sy1 += f1.y;
            sx2 += f2.x; sy2 += f2.y;
            sx3 += f3.x; sy3 += f3.y;
        }
    }
    float4 bva = ((const float4*)b)[lane * 2];
    float4 bvb = ((const float4*)b)[lane * 2 + 1];
    float v0 = bva.x + d * sx0, v1 = bva.y + d * sy0;
    float v2 = bva.z + d * sx1, v3 = bva.w + d * sy1;
    float v4 = bvb.x + d * sx2, v5 = bvb.y + d * sy2;
    float v6 = bvb.z + d * sx3, v7 = bvb.w + d * sy3;
    if (doRelu) {
        v0 = fmaxf(v0, 0.f); v1 = fmaxf(v1, 0.f);
        v2 = fmaxf(v2, 0.f); v3 = fmaxf(v3, 0.f);
        v4 = fmaxf(v4, 0.f); v5 = fmaxf(v5, 0.f);
        v6 = fmaxf(v6, 0.f); v7 = fmaxf(v7, 0.f);
    }
    ((uint4*)g_xb)[(size_t)n * 8 + lane] =
        make_uint4(pack_bf2(v0, v1), pack_bf2(v2, v3),
                   pack_bf2(v4, v5), pack_bf2(v6, v7));
}

// ---------------------------------------------------------------------------
// k_prededge: h = relu(A[u]+B[p]+b1); out = 5*sigmoid(h.W2 + b2)
// 8 lanes per edge (4 edges/warp); uint2 row reads (8B/lane = 8 fp8 cols).
// ---------------------------------------------------------------------------
__global__ __launch_bounds__(256) void k_prededge(
    const int* __restrict__ ei,
    const float* __restrict__ b1, const float* __restrict__ W2,
    const float* __restrict__ b2, float* __restrict__ out)
{
    __shared__ float b1s[64], w2s[64];
    __shared__ float b2v;
    int tid = threadIdx.x;
    if (tid < 64) { b1s[tid] = b1[tid]; w2s[tid] = W2[tid]; }
    if (tid == 0) b2v = b2[0];
    __syncthreads();

    int e = blockIdx.x * 32 + (tid >> 3);
    if (e >= NE) return;
    int lg = tid & 7;
    int u = ei[e];
    int p = ei[NE + e];
    uint2 ar = ((const uint2*)g_h8)[(size_t)u * 8 + lg];
    uint2 br = ((const uint2*)g_h8)[(size_t)(NU + p) * 8 + lg];
    float4 b1a = ((const float4*)b1s)[lg * 2];
    float4 b1b = ((const float4*)b1s)[lg * 2 + 1];
    float4 w2a = ((const float4*)w2s)[lg * 2];
    float4 w2b = ((const float4*)w2s)[lg * 2 + 1];
    float2 a0 = fp8x2_to_f2((unsigned short)(ar.x & 0xffffu));
    float2 a1 = fp8x2_to_f2((unsigned short)(ar.x >> 16));
    float2 a2 = fp8x2_to_f2((unsigned short)(ar.y & 0xffffu));
    float2 a3 = fp8x2_to_f2((unsigned short)(ar.y >> 16));
    float2 c0 = fp8x2_to_f2((unsigned short)(br.x & 0xffffu));
    float2 c1 = fp8x2_to_f2((unsigned short)(br.x >> 16));
    float2 c2 = fp8x2_to_f2((unsigned short)(br.y & 0xffffu));
    float2 c3 = fp8x2_to_f2((unsigned short)(br.y >> 16));
    float h0 = fmaxf(a0.x + c0.x + b1a.x, 0.f);
    float h1 = fmaxf(a0.y + c0.y + b1a.y, 0.f);
    float h2 = fmaxf(a1.x + c1.x + b1a.z, 0.f);
    float h3 = fmaxf(a1.y + c1.y + b1a.w, 0.f);
    float h4 = fmaxf(a2.x + c2.x + b1b.x, 0.f);
    float h5 = fmaxf(a2.y + c2.y + b1b.y, 0.f);
    float h6 = fmaxf(a3.x + c3.x + b1b.z, 0.f);
    float h7 = fmaxf(a3.y + c3.y + b1b.w, 0.f);
    float part = (h0 * w2a.x + h1 * w2a.y + h2 * w2a.z + h3 * w2a.w)
               + (h4 * w2b.x + h5 * w2b.y + h6 * w2b.z + h7 * w2b.w);
    #pragma unroll
    for (int off = 4; off; off >>= 1)
        part += __shfl_xor_sync(0xffffffffu, part, off);
    if (lg == 0) {
        float z = part + b2v;
        out[e] = 5.f / (1.f + expf(-z));
    }
}

// ---------------------------------------------------------------------------
extern "C" void kernel_launch(void* const* d_in, const int* in_sizes, int n_in,
                              void* d_out, int out_size)
{
    const int*   ei  = (const int*)d_in[0];   // [2, NE] int32
    const float* uf  = (const float*)d_in[1];
    const float* pf  = (const float*)d_in[2];
    const float* ue  = (const float*)d_in[3];
    const float* pe  = (const float*)d_in[4];
    const float* Wuf = (const float*)d_in[5];
    const float* buf_= (const float*)d_in[6];
    const float* Wpf = (const float*)d_in[7];
    const float* bpf = (const float*)d_in[8];
    const float* c1W = (const float*)d_in[9];
    const float* c1b = (const float*)d_in[10];
    const float* c2W = (const float*)d_in[11];
    const float* c2b = (const float*)d_in[12];
    const float* pW1 = (const float*)d_in[13];
    const float* pb1 = (const float*)d_in[14];
    const float* pW2 = (const float*)d_in[15];
    const float* pb2 = (const float*)d_in[16];
    float* out = (float*)d_out;

    const int AGU = NU / 32;   // agg blocks users (quarter-warp/node)
    const int AGP = NP / 32;   // agg blocks products (100000/32 = 3125)

    // Two-stream pipeline (streams/events leaked intentionally; capture-safe).
    cudaStream_t s2 = 0;
    cudaEvent_t ev[8] = {};
    bool par = (cudaStreamCreateWithFlags(&s2, cudaStreamNonBlocking) == cudaSuccess);
    for (int i = 0; par && i < 8; i++)
        par = (cudaEventCreateWithFlags(&ev[i], cudaEventDisableTiming) == cudaSuccess);

    if (par) {
        cudaEventRecord(ev[0], 0);
        cudaStreamWaitEvent(s2, ev[0], 0);

        k_zero <<<(NN + 255) / 256, 256, 0, s2>>>();
        k_build<<<(NE + 255) / 256, 256, 0, s2>>>(ei);
        cudaEventRecord(ev[1], s2);
        k_feat_t<<<GU, 256>>>(uf, pf, ue, pe, Wuf, buf_, Wpf, bpf, 0);
        k_feat_t<<<GP, 256, 0, s2>>>(uf, pf, ue, pe, Wuf, buf_, Wpf, bpf, GU);

        cudaStreamWaitEvent(0, ev[1], 0);
        k_mm<<<GU2, 256>>>(c1W, c1W, 1, 0);
        cudaEventRecord(ev[2], 0);
        k_mm<<<GP2, 256, 0, s2>>>(c1W, c1W, 1, GU2);
        cudaEventRecord(ev[3], s2);

        cudaStreamWaitEvent(0, ev[3], 0);
        k_agg<<<AGU, 256>>>(c1b, 1, 0, NU);
        k_mm <<<GU2, 256>>>(c2W, c2W, 1, 0);
        cudaEventRecord(ev[4], 0);
        cudaStreamWaitEvent(s2, ev[2], 0);
        k_agg<<<AGP, 256, 0, s2>>>(c1b, 1, NU, NP);
        k_mm <<<GP2, 256, 0, s2>>>(c2W, c2W, 1, GU2);
        cudaEventRecord(ev[5], s2);

        cudaStreamWaitEvent(0, ev[5], 0);
        k_agg<<<AGU, 256>>>(c2b, 0, 0, NU);
        k_mm <<<GU2, 256>>>(pW1, pW1 + 4096, 0, 0);
        cudaStreamWaitEvent(s2, ev[4], 0);
        k_agg<<<AGP, 256, 0, s2>>>(c2b, 0, NU, NP);
        k_mm <<<GP2, 256, 0, s2>>>(pW1, pW1 + 4096, 0, GU2);
        cudaEventRecord(ev[6], s2);

        cudaStreamWaitEvent(0, ev[6], 0);
        k_prededge<<<NE / 32, 256>>>(ei, pb1, pW2, pb2, out);
    } else {
        k_zero <<<(NN + 255) / 256, 256>>>();
        k_build<<<(NE + 255) / 256, 256>>>(ei);
        k_feat_t<<<GU + GP, 256>>>(uf, pf, ue, pe, Wuf, buf_, Wpf, bpf, 0);
        k_mm <<<GU2 + GP2, 256>>>(c1W, c1W, 1, 0);
        k_agg<<<NN / 32 + 1, 256>>>(c1b, 1, 0, NN);
        k_mm <<<GU2 + GP2, 256>>>(c2W, c2W, 1, 0);
        k_agg<<<NN / 32 + 1, 256>>>(c2b, 0, 0, NN);
        k_mm <<<GU2 + GP2, 256>>>(pW1, pW1 + 4096, 0, 0);
        k_prededge<<<NE / 32, 256>>>(ei, pb1, pW2, pb2, out);
    }
}

// round 16
// speedup vs baseline: 1.0347x; 1.0347x over previous
#include <cuda_runtime.h>
#include <cuda_bf16.h>
#include <cuda_fp8.h>
#include <cstdint>
#include <math.h>

#define NU 200000
#define NP 100000
#define NN 300000
#define NE 1000000
#define CAP 64             // adjacency slots per node (Poisson(~6.7): overflow impossible)
#define STRIDE 72          // bf16 units, padded row stride for 64-col smem tiles
#define XSTR 136           // bf16 units, padded row stride for 128-col feat tile
#define GU 1563            // ceil(NU/128)
#define GP 782             // ceil(NP/128)
#define GU2 782            // ceil(NU/256)  (mm: 256 rows/block)
#define GP2 391            // ceil(NP/256)

// Scratch (module-static device memory; sanctioned by harness rules)
__device__ __nv_bfloat162 g_xb[(size_t)NN * 32];     // GEMM inputs (bf16)
__device__ unsigned short g_h8[(size_t)NN * 32];     // messages / projections (fp8x2 e4m3)
__device__ int            g_cnt[NN];
__device__ int            g_adj[(size_t)NN * CAP];

// ---------------------------------------------------------------------------
// helpers
// ---------------------------------------------------------------------------
__device__ __forceinline__ unsigned pack_bf2(float x, float y) {
    __nv_bfloat162 h = __floats2bfloat162_rn(x, y);
    return *(unsigned*)&h;
}
__device__ __forceinline__ unsigned short f2_to_fp8x2(float x, float y) {
    float2 f = make_float2(x, y);
    return (unsigned short)__nv_cvt_float2_to_fp8x2(f, __NV_SATFINITE, __NV_E4M3);
}
__device__ __forceinline__ float2 fp8x2_to_f2(unsigned short v) {
    __half2_raw hr = __nv_cvt_fp8x2_to_halfraw2((__nv_fp8x2_storage_t)v, __NV_E4M3);
    return __half22float2(*(__half2*)&hr);
}

__device__ __forceinline__ void ldmA(uint32_t addr, uint32_t& a0, uint32_t& a1,
                                     uint32_t& a2, uint32_t& a3) {
    asm volatile("ldmatrix.sync.aligned.m8n8.x4.shared.b16 {%0,%1,%2,%3},[%4];"
                 : "=r"(a0), "=r"(a1), "=r"(a2), "=r"(a3) : "r"(addr));
}
__device__ __forceinline__ void ldmBT(uint32_t addr, uint32_t& b0, uint32_t& b1,
                                      uint32_t& b2, uint32_t& b3) {
    asm volatile("ldmatrix.sync.aligned.m8n8.x4.trans.shared.b16 {%0,%1,%2,%3},[%4];"
                 : "=r"(b0), "=r"(b1), "=r"(b2), "=r"(b3) : "r"(addr));
}
__device__ __forceinline__ void mma16816(float* c, uint32_t a0, uint32_t a1,
                                         uint32_t a2, uint32_t a3,
                                         uint32_t b0, uint32_t b1) {
    asm volatile("mma.sync.aligned.m16n8k16.row.col.f32.bf16.bf16.f32 "
                 "{%0,%1,%2,%3},{%4,%5,%6,%7},{%8,%9},{%0,%1,%2,%3};"
                 : "+f"(c[0]), "+f"(c[1]), "+f"(c[2]), "+f"(c[3])
                 : "r"(a0), "r"(a1), "r"(a2), "r"(a3), "r"(b0), "r"(b1));
}

// K-chunked core: C[warp 16 rows x 64 cols] += A[16 x 16*KS] @ B[16*KS x 64]
template<int KS, int ASTR>
__device__ __forceinline__ void mma_core_t(uint32_t xtw, uint32_t wtb, int l,
                                           float cf[8][4]) {
    uint32_t arow = (uint32_t)(((l & 7) + ((l >> 3) & 1) * 8));
    uint32_t aAddr = xtw + (arow * ASTR + (uint32_t)(l >> 4) * 8) * 2;
    uint32_t bAddr = wtb + (arow * STRIDE + (uint32_t)(l >> 4) * 8) * 2;
    #pragma unroll
    for (int ks = 0; ks < KS; ks++) {
        uint32_t a0, a1, a2, a3;
        ldmA(aAddr + ks * 32, a0, a1, a2, a3);
        #pragma unroll
        for (int np = 0; np < 4; np++) {
            uint32_t b0, b1, b2, b3;
            ldmBT(bAddr + (uint32_t)(ks * 16 * STRIDE + np * 16) * 2, b0, b1, b2, b3);
            mma16816(cf[2 * np],     a0, a1, a2, a3, b0, b1);
            mma16816(cf[2 * np + 1], a0, a1, a2, a3, b2, b3);
        }
    }
}

// ---------------------------------------------------------------------------
// Adjacency build
// ---------------------------------------------------------------------------
__global__ void k_zero() {
    int n = blockIdx.x * blockDim.x + threadIdx.x;
    if (n < NN) g_cnt[n] = 0;
}
__global__ void k_build(const int* __restrict__ ei) {
    int e = blockIdx.x * blockDim.x + threadIdx.x;
    if (e < NE) {
        int u = ei[e];
        int p = ei[NE + e];
        int s1 = atomicAdd(&g_cnt[u], 1);
        if (s1 < CAP) g_adj[(size_t)u * CAP + s1] = p;   // message p -> u
        int s2 = atomicAdd(&g_cnt[p], 1);
        if (s2 < CAP) g_adj[(size_t)p * CAP + s2] = u;   // message u -> p
    }
}

// ---------------------------------------------------------------------------
// Feature projection: g_xb[n] = bf16(feat[n](128) @ W + b + emb[n])
// Single K-pass; __launch_bounds__(256,3) = round-14 measured optimum.
// ---------------------------------------------------------------------------
__global__ __launch_bounds__(256, 3) void k_feat_t(
    const float* __restrict__ uf, const float* __restrict__ pf,
    const float* __restrict__ ue, const float* __restrict__ pe,
    const float* __restrict__ Wuf, const float* __restrict__ buf_,
    const float* __restrict__ Wpf, const float* __restrict__ bpf,
    int bidOff)
{
    __shared__ __align__(16) __nv_bfloat16 xt[128 * XSTR];   // 34.8 KB
    __shared__ __align__(16) __nv_bfloat16 wt[128 * STRIDE]; // 18.4 KB
    __shared__ float bs[64];

    int bid = blockIdx.x + bidOff;
    bool isUser = bid < GU;
    int lrow0 = isUser ? bid * 128 : (bid - GU) * 128;
    int nloc  = isUser ? NU : NP;
    const float* feat = isUser ? uf : pf;
    const float* emb  = isUser ? ue : pe;
    const float* W    = isUser ? Wuf : Wpf;
    const float* b    = isUser ? buf_ : bpf;
    int grow0 = isUser ? lrow0 : NU + lrow0;

    int tid = threadIdx.x;
    if (tid < 32) ((float2*)bs)[tid] = ((const float2*)b)[tid];

    const float4* W4 = (const float4*)W;
    const float4* f4 = (const float4*)feat;   // row stride 32 float4

    // W full (128x64 fp32 = 2048 f4), 8 per thread
    #pragma unroll
    for (int i = 0; i < 8; i++) {
        int idx = tid + i * 256, r = idx >> 4, c4 = idx & 15;
        float4 v = W4[idx];
        *(uint2*)(&wt[r * STRIDE + c4 * 4]) =
            make_uint2(pack_bf2(v.x, v.y), pack_bf2(v.z, v.w));
    }
    // x full (128 rows x 32 f4), 16 per thread
    #pragma unroll
    for (int i = 0; i < 16; i++) {
        int idx = tid + i * 256, r = idx >> 5, c4 = idx & 31;
        int lr = lrow0 + r;
        float4 v = make_float4(0.f, 0.f, 0.f, 0.f);
        if (lr < nloc) v = f4[(size_t)lr * 32 + c4];
        *(uint2*)(&xt[r * XSTR + c4 * 4]) =
            make_uint2(pack_bf2(v.x, v.y), pack_bf2(v.z, v.w));
    }
    __syncthreads();

    int l = tid & 31, w = tid >> 5;
    float cf[8][4];
    #pragma unroll
    for (int j = 0; j < 8; j++)
        #pragma unroll
        for (int q = 0; q < 4; q++) cf[j][q] = 0.f;

    mma_core_t<8, XSTR>(
        (uint32_t)__cvta_generic_to_shared(xt) + (uint32_t)(w * 16 * XSTR) * 2,
        (uint32_t)__cvta_generic_to_shared(wt), l, cf);

    int rl = w * 16 + (l >> 2);
    #pragma unroll
    for (int half = 0; half < 2; half++) {
        int lr = lrow0 + rl + half * 8;
        if (lr < nloc) {
            size_t gr = (size_t)(grow0 + rl + half * 8);
            #pragma unroll
            for (int j = 0; j < 8; j++) {
                int c2 = j * 4 + (l & 3);
                float2 ev = ((const float2*)emb)[(size_t)lr * 32 + c2];
                g_xb[gr * 32 + c2] = __floats2bfloat162_rn(
                    cf[j][half * 2 + 0] + bs[c2 * 2]     + ev.x,
                    cf[j][half * 2 + 1] + bs[c2 * 2 + 1] + ev.y);
            }
        }
    }
}

// ---------------------------------------------------------------------------
// k_mm: g_h8[n] = fp8( (g_xb[n] @ W) * (epiDis ? dis[n] : 1) )
// 256 rows/block (two 128-row tiles share one weight load).
// ---------------------------------------------------------------------------
__global__ __launch_bounds__(256) void k_mm(
    const float* __restrict__ Wu, const float* __restrict__ Wp, int epiDis,
    int bidOff)
{
    __shared__ __align__(16) __nv_bfloat16 xt[128 * STRIDE];
    __shared__ __align__(16) __nv_bfloat16 wt[64 * STRIDE];

    int bid = blockIdx.x + bidOff;
    bool isUser = bid < GU2;
    int lrow00 = isUser ? bid * 256 : (bid - GU2) * 256;
    int nloc  = isUser ? NU : NP;
    int gbase = isUser ? 0 : NU;
    const float* W = isUser ? Wu : Wp;

    int tid = threadIdx.x;
    #pragma unroll
    for (int i = 0; i < 4; i++) {
        int idx = tid + i * 256, r = idx >> 4, c4 = idx & 15;
        float4 v = ((const float4*)W)[idx];
        *(uint2*)(&wt[r * STRIDE + c4 * 4]) =
            make_uint2(pack_bf2(v.x, v.y), pack_bf2(v.z, v.w));
    }

    int l = tid & 31, w = tid >> 5;
    const uint4* x4 = (const uint4*)g_xb;

    #pragma unroll
    for (int t = 0; t < 2; t++) {
        int lrow0 = lrow00 + t * 128;
        __syncthreads();
        #pragma unroll
        for (int i = 0; i < 4; i++) {
            int idx = tid + i * 256, r = idx >> 3, c = idx & 7;
            int lr = lrow0 + r;
            uint4 v = make_uint4(0u, 0u, 0u, 0u);
            if (lr < nloc) v = x4[(size_t)(gbase + lr) * 8 + c];
            *(uint4*)(&xt[r * STRIDE + c * 8]) = v;
        }
        __syncthreads();

        float cf[8][4];
        #pragma unroll
        for (int j = 0; j < 8; j++)
            #pragma unroll
            for (int q = 0; q < 4; q++) cf[j][q] = 0.f;

        mma_core_t<4, STRIDE>(
            (uint32_t)__cvta_generic_to_shared(xt) + (uint32_t)(w * 16 * STRIDE) * 2,
            (uint32_t)__cvta_generic_to_shared(wt), l, cf);

        int rl = w * 16 + (l >> 2);
        #pragma unroll
        for (int half = 0; half < 2; half++) {
            int lr = lrow0 + rl + half * 8;
            if (lr < nloc) {
                int gr = gbase + lr;
                float d = epiDis ? rsqrtf((float)(g_cnt[gr] + 1)) : 1.f;
                #pragma unroll
                for (int j = 0; j < 8; j++) {
                    int c2 = j * 4 + (l & 3);
                    g_h8[(size_t)gr * 32 + c2] = f2_to_fp8x2(
                        cf[j][half * 2 + 0] * d, cf[j][half * 2 + 1] * d);
                }
            }
        }
    }
}

// ---------------------------------------------------------------------------
// k_agg: g_xb[n] = act( b + dis[n] * (g_h8[n] + sum_{src in adj[n]} g_h8[src]) )
// QUARTER-warp per node (fp8 rows are 64B = 8 lanes x 8B); 4 nodes per warp.
// ---------------------------------------------------------------------------
__global__ __launch_bounds__(256) void k_agg(const float* __restrict__ b,
                                             int doRelu, int nodeBase, int nNodes)
{
    int ln = blockIdx.x * 32 + (threadIdx.x >> 3);
    if (ln >= nNodes) return;
    int n = nodeBase + ln;
    int lane = threadIdx.x & 7;           // 8 fp8 cols => cols [8l,8l+8)
    int c = g_cnt[n];
    if (c > CAP) c = CAP;
    float d = rsqrtf((float)(c + 1));
    const uint2* h64 = (const uint2*)g_h8;   // 8B = 8 fp8 values
    uint2 own = h64[(size_t)n * 8 + lane];
    float2 s0v = fp8x2_to_f2((unsigned short)(own.x & 0xffffu));
    float2 s1v = fp8x2_to_f2((unsigned short)(own.x >> 16));
    float2 s2v = fp8x2_to_f2((unsigned short)(own.y & 0xffffu));
    float2 s3v = fp8x2_to_f2((unsigned short)(own.y >> 16));
    float sx0 = s0v.x, sy0 = s0v.y, sx1 = s1v.x, sy1 = s1v.y;
    float sx2 = s2v.x, sy2 = s2v.y, sx3 = s3v.x, sy3 = s3v.y;
    size_t base = (size_t)n * CAP;
    for (int i0 = 0; i0 < c; i0 += 8) {
        int m = min(8, c - i0);
        int srcl = (lane < m) ? g_adj[base + i0 + lane] : 0;
        int i = 0;
        for (; i + 3 < m; i += 4) {
            int a0 = __shfl_sync(0xffffffffu, srcl, i,     8);
            int a1 = __shfl_sync(0xffffffffu, srcl, i + 1, 8);
            int a2 = __shfl_sync(0xffffffffu, srcl, i + 2, 8);
            int a3 = __shfl_sync(0xffffffffu, srcl, i + 3, 8);
            uint2 r0 = h64[(size_t)a0 * 8 + lane];
            uint2 r1 = h64[(size_t)a1 * 8 + lane];
            uint2 r2 = h64[(size_t)a2 * 8 + lane];
            uint2 r3 = h64[(size_t)a3 * 8 + lane];
            #pragma unroll
            for (int q = 0; q < 4; q++) {
                uint2 rr = (q == 0) ? r0 : (q == 1) ? r1 : (q == 2) ? r2 : r3;
                float2 f0 = fp8x2_to_f2((unsigned short)(rr.x & 0xffffu));
                float2 f1 = fp8x2_to_f2((unsigned short)(rr.x >> 16));
                float2 f2 = fp8x2_to_f2((unsigned short)(rr.y & 0xffffu));
                float2 f3 = fp8x2_to_f2((unsigned short)(rr.y >> 16));
                sx0 += f0.x; sy0 += f0.y;
                sx1 += f1.x; sy1 += f1.y;
                sx2 += f2.x; sy2 += f2.y;
                sx3 += f3.x; sy3 += f3.y;
            }
        }
        for (; i < m; i++) {
            int a0 = __shfl_sync(0xffffffffu, srcl, i, 8);
            uint2 r0 = h64[(size_t)a0 * 8 + lane];
            float2 f0 = fp8x2_to_f2((unsigned short)(r0.x & 0xffffu));
            float2 f1 = fp8x2_to_f2((unsigned short)(r0.x >> 16));
            float2 f2 = fp8x2_to_f2((unsigned short)(r0.y & 0xffffu));
            float2 f3 = fp8x2_to_f2((unsigned short)(r0.y >> 16));
            sx0 += f0.x; sy0 += f0.y;
            sx1 += f1.x; sy1 += f1.y;
            sx2 += f2.x; sy2 += f2.y;
            sx3 += f3.x; sy3 += f3.y;
        }
    }
    float4 bva = ((const float4*)b)[lane * 2];
    float4 bvb = ((const float4*)b)[lane * 2 + 1];
    float v0 = bva.x + d * sx0, v1 = bva.y + d * sy0;
    float v2 = bva.z + d * sx1, v3 = bva.w + d * sy1;
    float v4 = bvb.x + d * sx2, v5 = bvb.y + d * sy2;
    float v6 = bvb.z + d * sx3, v7 = bvb.w + d * sy3;
    if (doRelu) {
        v0 = fmaxf(v0, 0.f); v1 = fmaxf(v1, 0.f);
        v2 = fmaxf(v2, 0.f); v3 = fmaxf(v3, 0.f);
        v4 = fmaxf(v4, 0.f); v5 = fmaxf(v5, 0.f);
        v6 = fmaxf(v6, 0.f); v7 = fmaxf(v7, 0.f);
    }
    ((uint4*)g_xb)[(size_t)n * 8 + lane] =
        make_uint4(pack_bf2(v0, v1), pack_bf2(v2, v3),
                   pack_bf2(v4, v5), pack_bf2(v6, v7));
}

// ---------------------------------------------------------------------------
// k_prededge: h = relu(A[u]+B[p]+b1); out = 5*sigmoid(h.W2 + b2)
// 8 lanes per edge (4 edges/warp); uint2 row reads (8B/lane = 8 fp8 cols).
// ---------------------------------------------------------------------------
__global__ __launch_bounds__(256) void k_prededge(
    const int* __restrict__ ei,
    const float* __restrict__ b1, const float* __restrict__ W2,
    const float* __restrict__ b2, float* __restrict__ out)
{
    __shared__ float b1s[64], w2s[64];
    __shared__ float b2v;
    int tid = threadIdx.x;
    if (tid < 64) { b1s[tid] = b1[tid]; w2s[tid] = W2[tid]; }
    if (tid == 0) b2v = b2[0];
    __syncthreads();

    int e = blockIdx.x * 32 + (tid >> 3);
    if (e >= NE) return;
    int lg = tid & 7;
    int u = ei[e];
    int p = ei[NE + e];
    uint2 ar = ((const uint2*)g_h8)[(size_t)u * 8 + lg];
    uint2 br = ((const uint2*)g_h8)[(size_t)(NU + p) * 8 + lg];
    float4 b1a = ((const float4*)b1s)[lg * 2];
    float4 b1b = ((const float4*)b1s)[lg * 2 + 1];
    float4 w2a = ((const float4*)w2s)[lg * 2];
    float4 w2b = ((const float4*)w2s)[lg * 2 + 1];
    float2 a0 = fp8x2_to_f2((unsigned short)(ar.x & 0xffffu));
    float2 a1 = fp8x2_to_f2((unsigned short)(ar.x >> 16));
    float2 a2 = fp8x2_to_f2((unsigned short)(ar.y & 0xffffu));
    float2 a3 = fp8x2_to_f2((unsigned short)(ar.y >> 16));
    float2 c0 = fp8x2_to_f2((unsigned short)(br.x & 0xffffu));
    float2 c1 = fp8x2_to_f2((unsigned short)(br.x >> 16));
    float2 c2 = fp8x2_to_f2((unsigned short)(br.y & 0xffffu));
    float2 c3 = fp8x2_to_f2((unsigned short)(br.y >> 16));
    float h0 = fmaxf(a0.x + c0.x + b1a.x, 0.f);
    float h1 = fmaxf(a0.y + c0.y + b1a.y, 0.f);
    float h2 = fmaxf(a1.x + c1.x + b1a.z, 0.f);
    float h3 = fmaxf(a1.y + c1.y + b1a.w, 0.f);
    float h4 = fmaxf(a2.x + c2.x + b1b.x, 0.f);
    float h5 = fmaxf(a2.y + c2.y + b1b.y, 0.f);
    float h6 = fmaxf(a3.x + c3.x + b1b.z, 0.f);
    float h7 = fmaxf(a3.y + c3.y + b1b.w, 0.f);
    float part = (h0 * w2a.x + h1 * w2a.y + h2 * w2a.z + h3 * w2a.w)
               + (h4 * w2b.x + h5 * w2b.y + h6 * w2b.z + h7 * w2b.w);
    #pragma unroll
    for (int off = 4; off; off >>= 1)
        part += __shfl_xor_sync(0xffffffffu, part, off);
    if (lg == 0) {
        float z = part + b2v;
        out[e] = 5.f / (1.f + expf(-z));
    }
}

// ---------------------------------------------------------------------------
extern "C" void kernel_launch(void* const* d_in, const int* in_sizes, int n_in,
                              void* d_out, int out_size)
{
    const int*   ei  = (const int*)d_in[0];   // [2, NE] int32
    const float* uf  = (const float*)d_in[1];
    const float* pf  = (const float*)d_in[2];
    const float* ue  = (const float*)d_in[3];
    const float* pe  = (const float*)d_in[4];
    const float* Wuf = (const float*)d_in[5];
    const float* buf_= (const float*)d_in[6];
    const float* Wpf = (const float*)d_in[7];
    const float* bpf = (const float*)d_in[8];
    const float* c1W = (const float*)d_in[9];
    const float* c1b = (const float*)d_in[10];
    const float* c2W = (const float*)d_in[11];
    const float* c2b = (const float*)d_in[12];
    const float* pW1 = (const float*)d_in[13];
    const float* pb1 = (const float*)d_in[14];
    const float* pW2 = (const float*)d_in[15];
    const float* pb2 = (const float*)d_in[16];
    float* out = (float*)d_out;

    const int AGU = NU / 32;   // agg blocks users (quarter-warp/node)
    const int AGP = NP / 32;   // agg blocks products

    // Two-stream pipeline (streams/events leaked intentionally; capture-safe).
    cudaStream_t s2 = 0;
    cudaEvent_t ev[8] = {};
    bool par = (cudaStreamCreateWithFlags(&s2, cudaStreamNonBlocking) == cudaSuccess);
    for (int i = 0; par && i < 8; i++)
        par = (cudaEventCreateWithFlags(&ev[i], cudaEventDisableTiming) == cudaSuccess);

    if (par) {
        cudaEventRecord(ev[0], 0);
        cudaStreamWaitEvent(s2, ev[0], 0);

        k_zero <<<(NN + 255) / 256, 256, 0, s2>>>();
        k_build<<<(NE + 255) / 256, 256, 0, s2>>>(ei);
        cudaEventRecord(ev[1], s2);
        k_feat_t<<<GU, 256>>>(uf, pf, ue, pe, Wuf, buf_, Wpf, bpf, 0);
        k_feat_t<<<GP, 256, 0, s2>>>(uf, pf, ue, pe, Wuf, buf_, Wpf, bpf, GU);

        cudaStreamWaitEvent(0, ev[1], 0);
        k_mm<<<GU2, 256>>>(c1W, c1W, 1, 0);
        cudaEventRecord(ev[2], 0);
        k_mm<<<GP2, 256, 0, s2>>>(c1W, c1W, 1, GU2);
        cudaEventRecord(ev[3], s2);

        cudaStreamWaitEvent(0, ev[3], 0);
        k_agg<<<AGU, 256>>>(c1b, 1, 0, NU);
        k_mm <<<GU2, 256>>>(c2W, c2W, 1, 0);
        cudaEventRecord(ev[4], 0);
        cudaStreamWaitEvent(s2, ev[2], 0);
        k_agg<<<AGP, 256, 0, s2>>>(c1b, 1, NU, NP);
        k_mm <<<GP2, 256, 0, s2>>>(c2W, c2W, 1, GU2);
        cudaEventRecord(ev[5], s2);

        cudaStreamWaitEvent(0, ev[5], 0);
        k_agg<<<AGU, 256>>>(c2b, 0, 0, NU);
        k_mm <<<GU2, 256>>>(pW1, pW1 + 4096, 0, 0);
        cudaStreamWaitEvent(s2, ev[4], 0);
        k_agg<<<AGP, 256, 0, s2>>>(c2b, 0, NU, NP);
        k_mm <<<GP2, 256, 0, s2>>>(pW1, pW1 + 4096, 0, GU2);
        cudaEventRecord(ev[6], s2);

        cudaStreamWaitEvent(0, ev[6], 0);
        k_prededge<<<NE / 32, 256>>>(ei, pb1, pW2, pb2, out);
    } else {
        k_zero <<<(NN + 255) / 256, 256>>>();
        k_build<<<(NE + 255) / 256, 256>>>(ei);
        k_feat_t<<<GU + GP, 256>>>(uf, pf, ue, pe, Wuf, buf_, Wpf, bpf, 0);
        k_mm <<<GU2 + GP2, 256>>>(c1W, c1W, 1, 0);
        k_agg<<<NN / 32 + 1, 256>>>(c1b, 1, 0, NN);
        k_mm <<<GU2 + GP2, 256>>>(c2W, c2W, 1, 0);
        k_agg<<<NN / 32 + 1, 256>>>(c2b, 0, 0, NN);
        k_mm <<<GU2 + GP2, 256>>>(pW1, pW1 + 4096, 0, 0);
        k_prededge<<<NE / 32, 256>>>(ei, pb1, pW2, pb2, out);
    }
}

// round 17
// speedup vs baseline: 1.1034x; 1.0665x over previous
#include <cuda_runtime.h>
#include <cuda_bf16.h>
#include <cuda_fp8.h>
#include <cstdint>
#include <math.h>

#define NU 200000
#define NP 100000
#define NN 300000
#define NE 1000000
#define CAP 64             // adjacency slots per node (Poisson(~6.7): overflow impossible)
#define STRIDE 72          // bf16 units, padded row stride for 64-col smem tiles
#define XSTR 136           // bf16 units, padded row stride for 128-col feat tile
#define GU 1563            // ceil(NU/128)
#define GP 782             // ceil(NP/128)
#define GU2 782            // ceil(NU/256)  (mm: 256 rows/block)
#define GP2 391            // ceil(NP/256)

// Scratch (module-static device memory; sanctioned by harness rules)
__device__ __nv_bfloat162 g_xb[(size_t)NN * 32];     // GEMM inputs (bf16)
__device__ unsigned short g_h8[(size_t)NN * 32];     // messages / projections (fp8x2 e4m3)
__device__ int            g_cnt[NN];
__device__ int            g_adj[(size_t)NN * CAP];

// ---------------------------------------------------------------------------
// helpers
// ---------------------------------------------------------------------------
__device__ __forceinline__ unsigned pack_bf2(float x, float y) {
    __nv_bfloat162 h = __floats2bfloat162_rn(x, y);
    return *(unsigned*)&h;
}
__device__ __forceinline__ unsigned short f2_to_fp8x2(float x, float y) {
    float2 f = make_float2(x, y);
    return (unsigned short)__nv_cvt_float2_to_fp8x2(f, __NV_SATFINITE, __NV_E4M3);
}
__device__ __forceinline__ float2 fp8x2_to_f2(unsigned short v) {
    __half2_raw hr = __nv_cvt_fp8x2_to_halfraw2((__nv_fp8x2_storage_t)v, __NV_E4M3);
    return __half22float2(*(__half2*)&hr);
}

__device__ __forceinline__ void ldmA(uint32_t addr, uint32_t& a0, uint32_t& a1,
                                     uint32_t& a2, uint32_t& a3) {
    asm volatile("ldmatrix.sync.aligned.m8n8.x4.shared.b16 {%0,%1,%2,%3},[%4];"
                 : "=r"(a0), "=r"(a1), "=r"(a2), "=r"(a3) : "r"(addr));
}
__device__ __forceinline__ void ldmBT(uint32_t addr, uint32_t& b0, uint32_t& b1,
                                      uint32_t& b2, uint32_t& b3) {
    asm volatile("ldmatrix.sync.aligned.m8n8.x4.trans.shared.b16 {%0,%1,%2,%3},[%4];"
                 : "=r"(b0), "=r"(b1), "=r"(b2), "=r"(b3) : "r"(addr));
}
__device__ __forceinline__ void mma16816(float* c, uint32_t a0, uint32_t a1,
                                         uint32_t a2, uint32_t a3,
                                         uint32_t b0, uint32_t b1) {
    asm volatile("mma.sync.aligned.m16n8k16.row.col.f32.bf16.bf16.f32 "
                 "{%0,%1,%2,%3},{%4,%5,%6,%7},{%8,%9},{%0,%1,%2,%3};"
                 : "+f"(c[0]), "+f"(c[1]), "+f"(c[2]), "+f"(c[3])
                 : "r"(a0), "r"(a1), "r"(a2), "r"(a3), "r"(b0), "r"(b1));
}

// K-chunked core: C[warp 16 rows x 64 cols] += A[16 x 16*KS] @ B[16*KS x 64]
template<int KS, int ASTR>
__device__ __forceinline__ void mma_core_t(uint32_t xtw, uint32_t wtb, int l,
                                           float cf[8][4]) {
    uint32_t arow = (uint32_t)(((l & 7) + ((l >> 3) & 1) * 8));
    uint32_t aAddr = xtw + (arow * ASTR + (uint32_t)(l >> 4) * 8) * 2;
    uint32_t bAddr = wtb + (arow * STRIDE + (uint32_t)(l >> 4) * 8) * 2;
    #pragma unroll
    for (int ks = 0; ks < KS; ks++) {
        uint32_t a0, a1, a2, a3;
        ldmA(aAddr + ks * 32, a0, a1, a2, a3);
        #pragma unroll
        for (int np = 0; np < 4; np++) {
            uint32_t b0, b1, b2, b3;
            ldmBT(bAddr + (uint32_t)(ks * 16 * STRIDE + np * 16) * 2, b0, b1, b2, b3);
            mma16816(cf[2 * np],     a0, a1, a2, a3, b0, b1);
            mma16816(cf[2 * np + 1], a0, a1, a2, a3, b2, b3);
        }
    }
}

// ---------------------------------------------------------------------------
// Adjacency build
// ---------------------------------------------------------------------------
__global__ void k_zero() {
    int n = blockIdx.x * blockDim.x + threadIdx.x;
    if (n < NN) g_cnt[n] = 0;
}
__global__ void k_build(const int* __restrict__ ei) {
    int e = blockIdx.x * blockDim.x + threadIdx.x;
    if (e < NE) {
        int u = ei[e];
        int p = ei[NE + e];
        int s1 = atomicAdd(&g_cnt[u], 1);
        if (s1 < CAP) g_adj[(size_t)u * CAP + s1] = p;   // message p -> u
        int s2 = atomicAdd(&g_cnt[p], 1);
        if (s2 < CAP) g_adj[(size_t)p * CAP + s2] = u;   // message u -> p
    }
}

// ---------------------------------------------------------------------------
// Feature projection: g_xb[n] = bf16(feat[n](128) @ W + b + emb[n])
// Single K-pass; __launch_bounds__(256,3) = measured optimum (do not change).
// ---------------------------------------------------------------------------
__global__ __launch_bounds__(256, 3) void k_feat_t(
    const float* __restrict__ uf, const float* __restrict__ pf,
    const float* __restrict__ ue, const float* __restrict__ pe,
    const float* __restrict__ Wuf, const float* __restrict__ buf_,
    const float* __restrict__ Wpf, const float* __restrict__ bpf,
    int bidOff)
{
    __shared__ __align__(16) __nv_bfloat16 xt[128 * XSTR];   // 34.8 KB
    __shared__ __align__(16) __nv_bfloat16 wt[128 * STRIDE]; // 18.4 KB
    __shared__ float bs[64];

    int bid = blockIdx.x + bidOff;
    bool isUser = bid < GU;
    int lrow0 = isUser ? bid * 128 : (bid - GU) * 128;
    int nloc  = isUser ? NU : NP;
    const float* feat = isUser ? uf : pf;
    const float* emb  = isUser ? ue : pe;
    const float* W    = isUser ? Wuf : Wpf;
    const float* b    = isUser ? buf_ : bpf;
    int grow0 = isUser ? lrow0 : NU + lrow0;

    int tid = threadIdx.x;
    if (tid < 32) ((float2*)bs)[tid] = ((const float2*)b)[tid];

    const float4* W4 = (const float4*)W;
    const float4* f4 = (const float4*)feat;   // row stride 32 float4

    #pragma unroll
    for (int i = 0; i < 8; i++) {
        int idx = tid + i * 256, r = idx >> 4, c4 = idx & 15;
        float4 v = W4[idx];
        *(uint2*)(&wt[r * STRIDE + c4 * 4]) =
            make_uint2(pack_bf2(v.x, v.y), pack_bf2(v.z, v.w));
    }
    #pragma unroll
    for (int i = 0; i < 16; i++) {
        int idx = tid + i * 256, r = idx >> 5, c4 = idx & 31;
        int lr = lrow0 + r;
        float4 v = make_float4(0.f, 0.f, 0.f, 0.f);
        if (lr < nloc) v = f4[(size_t)lr * 32 + c4];
        *(uint2*)(&xt[r * XSTR + c4 * 4]) =
            make_uint2(pack_bf2(v.x, v.y), pack_bf2(v.z, v.w));
    }
    __syncthreads();

    int l = tid & 31, w = tid >> 5;
    float cf[8][4];
    #pragma unroll
    for (int j = 0; j < 8; j++)
        #pragma unroll
        for (int q = 0; q < 4; q++) cf[j][q] = 0.f;

    mma_core_t<8, XSTR>(
        (uint32_t)__cvta_generic_to_shared(xt) + (uint32_t)(w * 16 * XSTR) * 2,
        (uint32_t)__cvta_generic_to_shared(wt), l, cf);

    int rl = w * 16 + (l >> 2);
    #pragma unroll
    for (int half = 0; half < 2; half++) {
        int lr = lrow0 + rl + half * 8;
        if (lr < nloc) {
            size_t gr = (size_t)(grow0 + rl + half * 8);
            #pragma unroll
            for (int j = 0; j < 8; j++) {
                int c2 = j * 4 + (l & 3);
                float2 ev = ((const float2*)emb)[(size_t)lr * 32 + c2];
                g_xb[gr * 32 + c2] = __floats2bfloat162_rn(
                    cf[j][half * 2 + 0] + bs[c2 * 2]     + ev.x,
                    cf[j][half * 2 + 1] + bs[c2 * 2 + 1] + ev.y);
            }
        }
    }
}

// ---------------------------------------------------------------------------
// k_mm: g_h8[n] = fp8( (g_xb[n] @ W) * (epiDis ? dis[n] : 1) )
// 256 rows/block; tile-1 global loads overlapped with tile-0 MMA (2 buffers).
// ---------------------------------------------------------------------------
__global__ __launch_bounds__(256) void k_mm(
    const float* __restrict__ Wu, const float* __restrict__ Wp, int epiDis,
    int bidOff)
{
    __shared__ __align__(16) __nv_bfloat16 xt0[128 * STRIDE];
    __shared__ __align__(16) __nv_bfloat16 xt1[128 * STRIDE];
    __shared__ __align__(16) __nv_bfloat16 wt[64 * STRIDE];

    int bid = blockIdx.x + bidOff;
    bool isUser = bid < GU2;
    int lrow00 = isUser ? bid * 256 : (bid - GU2) * 256;
    int nloc  = isUser ? NU : NP;
    int gbase = isUser ? 0 : NU;
    const float* W = isUser ? Wu : Wp;

    int tid = threadIdx.x;
    #pragma unroll
    for (int i = 0; i < 4; i++) {
        int idx = tid + i * 256, r = idx >> 4, c4 = idx & 15;
        float4 v = ((const float4*)W)[idx];
        *(uint2*)(&wt[r * STRIDE + c4 * 4]) =
            make_uint2(pack_bf2(v.x, v.y), pack_bf2(v.z, v.w));
    }

    int l = tid & 31, w = tid >> 5;
    const uint4* x4 = (const uint4*)g_xb;
    uint32_t wtb = (uint32_t)__cvta_generic_to_shared(wt);

    // tile 0 load -> smem
    #pragma unroll
    for (int i = 0; i < 4; i++) {
        int idx = tid + i * 256, r = idx >> 3, c = idx & 7;
        int lr = lrow00 + r;
        uint4 v = make_uint4(0u, 0u, 0u, 0u);
        if (lr < nloc) v = x4[(size_t)(gbase + lr) * 8 + c];
        *(uint4*)(&xt0[r * STRIDE + c * 8]) = v;
    }
    __syncthreads();

    // issue tile 1 global loads NOW (fly under tile-0 MMA)
    uint4 t1v[4];
    #pragma unroll
    for (int i = 0; i < 4; i++) {
        int idx = tid + i * 256, r = idx >> 3;
        int lr = lrow00 + 128 + r;
        t1v[i] = make_uint4(0u, 0u, 0u, 0u);
        if (lr < nloc) t1v[i] = x4[(size_t)(gbase + lr) * 8 + (idx & 7)];
    }

    // MMA + epilogue tile 0
    {
        float cf[8][4];
        #pragma unroll
        for (int j = 0; j < 8; j++)
            #pragma unroll
            for (int q = 0; q < 4; q++) cf[j][q] = 0.f;
        mma_core_t<4, STRIDE>(
            (uint32_t)__cvta_generic_to_shared(xt0) + (uint32_t)(w * 16 * STRIDE) * 2,
            wtb, l, cf);
        int rl = w * 16 + (l >> 2);
        #pragma unroll
        for (int half = 0; half < 2; half++) {
            int lr = lrow00 + rl + half * 8;
            if (lr < nloc) {
                int gr = gbase + lr;
                float d = epiDis ? rsqrtf((float)(g_cnt[gr] + 1)) : 1.f;
                #pragma unroll
                for (int j = 0; j < 8; j++) {
                    int c2 = j * 4 + (l & 3);
                    g_h8[(size_t)gr * 32 + c2] = f2_to_fp8x2(
                        cf[j][half * 2 + 0] * d, cf[j][half * 2 + 1] * d);
                }
            }
        }
    }

    // store tile 1 to its own buffer (no sync needed before: different buffer)
    #pragma unroll
    for (int i = 0; i < 4; i++) {
        int idx = tid + i * 256, r = idx >> 3, c = idx & 7;
        *(uint4*)(&xt1[r * STRIDE + c * 8]) = t1v[i];
    }
    __syncthreads();

    // MMA + epilogue tile 1
    {
        float cf[8][4];
        #pragma unroll
        for (int j = 0; j < 8; j++)
            #pragma unroll
            for (int q = 0; q < 4; q++) cf[j][q] = 0.f;
        mma_core_t<4, STRIDE>(
            (uint32_t)__cvta_generic_to_shared(xt1) + (uint32_t)(w * 16 * STRIDE) * 2,
            wtb, l, cf);
        int rl = w * 16 + (l >> 2);
        #pragma unroll
        for (int half = 0; half < 2; half++) {
            int lr = lrow00 + 128 + rl + half * 8;
            if (lr < nloc) {
                int gr = gbase + lr;
                float d = epiDis ? rsqrtf((float)(g_cnt[gr] + 1)) : 1.f;
                #pragma unroll
                for (int j = 0; j < 8; j++) {
                    int c2 = j * 4 + (l & 3);
                    g_h8[(size_t)gr * 32 + c2] = f2_to_fp8x2(
                        cf[j][half * 2 + 0] * d, cf[j][half * 2 + 1] * d);
                }
            }
        }
    }
}

// ---------------------------------------------------------------------------
// k_agg: g_xb[n] = act( b + dis[n] * (g_h8[n] + sum_{src in adj[n]} g_h8[src]) )
// QUARTER-warp per node (fp8 rows are 64B = 8 lanes x 8B); 4 nodes per warp.
// ---------------------------------------------------------------------------
__global__ __launch_bounds__(256) void k_agg(const float* __restrict__ b,
                                             int doRelu, int nodeBase, int nNodes)
{
    int ln = blockIdx.x * 32 + (threadIdx.x >> 3);
    if (ln >= nNodes) return;
    int n = nodeBase + ln;
    int lane = threadIdx.x & 7;           // 8 fp8 cols => cols [8l,8l+8)
    int c = g_cnt[n];
    if (c > CAP) c = CAP;
    float d = rsqrtf((float)(c + 1));
    const uint2* h64 = (const uint2*)g_h8;   // 8B = 8 fp8 values
    uint2 own = h64[(size_t)n * 8 + lane];
    float2 s0v = fp8x2_to_f2((unsigned short)(own.x & 0xffffu));
    float2 s1v = fp8x2_to_f2((unsigned short)(own.x >> 16));
    float2 s2v = fp8x2_to_f2((unsigned short)(own.y & 0xffffu));
    float2 s3v = fp8x2_to_f2((unsigned short)(own.y >> 16));
    float sx0 = s0v.x, sy0 = s0v.y, sx1 = s1v.x, sy1 = s1v.y;
    float sx2 = s2v.x, sy2 = s2v.y, sx3 = s3v.x, sy3 = s3v.y;
    size_t base = (size_t)n * CAP;
    for (int i0 = 0; i0 < c; i0 += 8) {
        int m = min(8, c - i0);
        int srcl = (lane < m) ? g_adj[base + i0 + lane] : 0;
        int i = 0;
        for (; i + 3 < m; i += 4) {
            int a0 = __shfl_sync(0xffffffffu, srcl, i,     8);
            int a1 = __shfl_sync(0xffffffffu, srcl, i + 1, 8);
            int a2 = __shfl_sync(0xffffffffu, srcl, i + 2, 8);
            int a3 = __shfl_sync(0xffffffffu, srcl, i + 3, 8);
            uint2 r0 = h64[(size_t)a0 * 8 + lane];
            uint2 r1 = h64[(size_t)a1 * 8 + lane];
            uint2 r2 = h64[(size_t)a2 * 8 + lane];
            uint2 r3 = h64[(size_t)a3 * 8 + lane];
            #pragma unroll
            for (int q = 0; q < 4; q++) {
                uint2 rr = (q == 0) ? r0 : (q == 1) ? r1 : (q == 2) ? r2 : r3;
                float2 f0 = fp8x2_to_f2((unsigned short)(rr.x & 0xffffu));
                float2 f1 = fp8x2_to_f2((unsigned short)(rr.x >> 16));
                float2 f2 = fp8x2_to_f2((unsigned short)(rr.y & 0xffffu));
                float2 f3 = fp8x2_to_f2((unsigned short)(rr.y >> 16));
                sx0 += f0.x; sy0 += f0.y;
                sx1 += f1.x; sy1 += f1.y;
                sx2 += f2.x; sy2 += f2.y;
                sx3 += f3.x; sy3 += f3.y;
            }
        }
        for (; i < m; i++) {
            int a0 = __shfl_sync(0xffffffffu, srcl, i, 8);
            uint2 r0 = h64[(size_t)a0 * 8 + lane];
            float2 f0 = fp8x2_to_f2((unsigned short)(r0.x & 0xffffu));
            float2 f1 = fp8x2_to_f2((unsigned short)(r0.x >> 16));
            float2 f2 = fp8x2_to_f2((unsigned short)(r0.y & 0xffffu));
            float2 f3 = fp8x2_to_f2((unsigned short)(r0.y >> 16));
            sx0 += f0.x; sy0 += f0.y;
            sx1 += f1.x; sy1 += f1.y;
            sx2 += f2.x; sy2 += f2.y;
            sx3 += f3.x; sy3 += f3.y;
        }
    }
    float4 bva = ((const float4*)b)[lane * 2];
    float4 bvb = ((const float4*)b)[lane * 2 + 1];
    float v0 = bva.x + d * sx0, v1 = bva.y + d * sy0;
    float v2 = bva.z + d * sx1, v3 = bva.w + d * sy1;
    float v4 = bvb.x + d * sx2, v5 = bvb.y + d * sy2;
    float v6 = bvb.z + d * sx3, v7 = bvb.w + d * sy3;
    if (doRelu) {
        v0 = fmaxf(v0, 0.f); v1 = fmaxf(v1, 0.f);
        v2 = fmaxf(v2, 0.f); v3 = fmaxf(v3, 0.f);
        v4 = fmaxf(v4, 0.f); v5 = fmaxf(v5, 0.f);
        v6 = fmaxf(v6, 0.f); v7 = fmaxf(v7, 0.f);
    }
    ((uint4*)g_xb)[(size_t)n * 8 + lane] =
        make_uint4(pack_bf2(v0, v1), pack_bf2(v2, v3),
                   pack_bf2(v4, v5), pack_bf2(v6, v7));
}

// ---------------------------------------------------------------------------
// k_prededge: h = relu(A[u]+B[p]+b1); out = 5*sigmoid(h.W2 + b2)
// 4 lanes per edge (8 edges/warp); uint4 row reads (16B/lane = 16 fp8 cols).
// ---------------------------------------------------------------------------
__global__ __launch_bounds__(256) void k_prededge(
    const int* __restrict__ ei,
    const float* __restrict__ b1, const float* __restrict__ W2,
    const float* __restrict__ b2, float* __restrict__ out)
{
    __shared__ float b1s[64], w2s[64];
    __shared__ float b2v;
    int tid = threadIdx.x;
    if (tid < 64) { b1s[tid] = b1[tid]; w2s[tid] = W2[tid]; }
    if (tid == 0) b2v = b2[0];
    __syncthreads();

    int e = blockIdx.x * 64 + (tid >> 2);
    if (e >= NE) return;
    int lg = tid & 3;            // 4 lanes/edge, 16 fp8 cols per lane
    int u = ei[e];
    int p = ei[NE + e];
    uint4 ar = ((const uint4*)g_h8)[(size_t)u * 4 + lg];
    uint4 br = ((const uint4*)g_h8)[(size_t)(NU + p) * 4 + lg];
    float part = 0.f;
    const unsigned* arp = (const unsigned*)&ar;
    const unsigned* brp = (const unsigned*)&br;
    #pragma unroll
    for (int q = 0; q < 4; q++) {
        float4 b1v = ((const float4*)b1s)[lg * 4 + q];
        float4 w2v = ((const float4*)w2s)[lg * 4 + q];
        float2 a0 = fp8x2_to_f2((unsigned short)(arp[q] & 0xffffu));
        float2 a1 = fp8x2_to_f2((unsigned short)(arp[q] >> 16));
        float2 c0 = fp8x2_to_f2((unsigned short)(brp[q] & 0xffffu));
        float2 c1 = fp8x2_to_f2((unsigned short)(brp[q] >> 16));
        float h0 = fmaxf(a0.x + c0.x + b1v.x, 0.f);
        float h1 = fmaxf(a0.y + c0.y + b1v.y, 0.f);
        float h2 = fmaxf(a1.x + c1.x + b1v.z, 0.f);
        float h3 = fmaxf(a1.y + c1.y + b1v.w, 0.f);
        part += h0 * w2v.x + h1 * w2v.y + h2 * w2v.z + h3 * w2v.w;
    }
    #pragma unroll
    for (int off = 2; off; off >>= 1)
        part += __shfl_xor_sync(0xffffffffu, part, off);
    if (lg == 0) {
        float z = part + b2v;
        out[e] = 5.f / (1.f + expf(-z));
    }
}

// ---------------------------------------------------------------------------
extern "C" void kernel_launch(void* const* d_in, const int* in_sizes, int n_in,
                              void* d_out, int out_size)
{
    const int*   ei  = (const int*)d_in[0];   // [2, NE] int32
    const float* uf  = (const float*)d_in[1];
    const float* pf  = (const float*)d_in[2];
    const float* ue  = (const float*)d_in[3];
    const float* pe  = (const float*)d_in[4];
    const float* Wuf = (const float*)d_in[5];
    const float* buf_= (const float*)d_in[6];
    const float* Wpf = (const float*)d_in[7];
    const float* bpf = (const float*)d_in[8];
    const float* c1W = (const float*)d_in[9];
    const float* c1b = (const float*)d_in[10];
    const float* c2W = (const float*)d_in[11];
    const float* c2b = (const float*)d_in[12];
    const float* pW1 = (const float*)d_in[13];
    const float* pb1 = (const float*)d_in[14];
    const float* pW2 = (const float*)d_in[15];
    const float* pb2 = (const float*)d_in[16];
    float* out = (float*)d_out;

    const int AGU = NU / 32;   // agg blocks users (quarter-warp/node)
    const int AGP = NP / 32;   // agg blocks products

    // Two-stream pipeline (streams/events leaked intentionally; capture-safe).
    cudaStream_t s2 = 0;
    cudaEvent_t ev[8] = {};
    bool par = (cudaStreamCreateWithFlags(&s2, cudaStreamNonBlocking) == cudaSuccess);
    for (int i = 0; par && i < 8; i++)
        par = (cudaEventCreateWithFlags(&ev[i], cudaEventDisableTiming) == cudaSuccess);

    if (par) {
        cudaEventRecord(ev[0], 0);
        cudaStreamWaitEvent(s2, ev[0], 0);

        k_zero <<<(NN + 255) / 256, 256, 0, s2>>>();
        k_build<<<(NE + 255) / 256, 256, 0, s2>>>(ei);
        cudaEventRecord(ev[1], s2);
        k_feat_t<<<GU, 256>>>(uf, pf, ue, pe, Wuf, buf_, Wpf, bpf, 0);
        k_feat_t<<<GP, 256, 0, s2>>>(uf, pf, ue, pe, Wuf, buf_, Wpf, bpf, GU);

        cudaStreamWaitEvent(0, ev[1], 0);
        k_mm<<<GU2, 256>>>(c1W, c1W, 1, 0);
        cudaEventRecord(ev[2], 0);
        k_mm<<<GP2, 256, 0, s2>>>(c1W, c1W, 1, GU2);
        cudaEventRecord(ev[3], s2);

        cudaStreamWaitEvent(0, ev[3], 0);
        k_agg<<<AGU, 256>>>(c1b, 1, 0, NU);
        k_mm <<<GU2, 256>>>(c2W, c2W, 1, 0);
        cudaEventRecord(ev[4], 0);
        cudaStreamWaitEvent(s2, ev[2], 0);
        k_agg<<<AGP, 256, 0, s2>>>(c1b, 1, NU, NP);
        k_mm <<<GP2, 256, 0, s2>>>(c2W, c2W, 1, GU2);
        cudaEventRecord(ev[5], s2);

        cudaStreamWaitEvent(0, ev[5], 0);
        k_agg<<<AGU, 256>>>(c2b, 0, 0, NU);
        k_mm <<<GU2, 256>>>(pW1, pW1 + 4096, 0, 0);
        cudaStreamWaitEvent(s2, ev[4], 0);
        k_agg<<<AGP, 256, 0, s2>>>(c2b, 0, NU, NP);
        k_mm <<<GP2, 256, 0, s2>>>(pW1, pW1 + 4096, 0, GU2);
        cudaEventRecord(ev[6], s2);

        cudaStreamWaitEvent(0, ev[6], 0);
        k_prededge<<<NE / 64, 256>>>(ei, pb1, pW2, pb2, out);
    } else {
        k_zero <<<(NN + 255) / 256, 256>>>();
        k_build<<<(NE + 255) / 256, 256>>>(ei);
        k_feat_t<<<GU + GP, 256>>>(uf, pf, ue, pe, Wuf, buf_, Wpf, bpf, 0);
        k_mm <<<GU2 + GP2, 256>>>(c1W, c1W, 1, 0);
        k_agg<<<NN / 32 + 1, 256>>>(c1b, 1, 0, NN);
        k_mm <<<GU2 + GP2, 256>>>(c2W, c2W, 1, 0);
        k_agg<<<NN / 32 + 1, 256>>>(c2b, 0, 0, NN);
        k_mm <<<GU2 + GP2, 256>>>(pW1, pW1 + 4096, 0, 0);
        k_prededge<<<NE / 64, 256>>>(ei, pb1, pW2, pb2, out);
    }
}